// round 7
// baseline (speedup 1.0000x reference)
#include <cuda_runtime.h>
#include <math.h>

#define N_POINTS   4194304
#define NUM_LEVELS 16
#define HASH_MASK  ((1u << 19) - 1u)
#define THREADS    1024
#define CTAS       148            // persistent: one CTA per SM (B300 count; safe on GB300)
#define NGROUPS    (N_POINTS / 4) // 4 points per warp-iteration

struct Params {
    float rm1[NUM_LEVELS];
    int   res0, res1, n0, ncells;   // dense-cache dims for levels 0,1
};

extern __shared__ float2 s_tab[];   // [res0^3 + res1^3] dense level-0/1 cache

__global__ __launch_bounds__(THREADS, 1)
void hashenc_kernel(const float*  __restrict__ pts,
                    const float*  __restrict__ tables,
                    float*        __restrict__ out,
                    Params pp)
{
    const float2* tb = reinterpret_cast<const float2*>(tables);

    // ---- Build dense smem caches for levels 0 and 1 (once per persistent CTA).
    // Cell (cx,cy,cz) -> value tables[l][hash(cx,cy,cz)], stored at dense index
    // (cx*r + cy)*r + cz (+ n0 for level 1).
    for (int c = threadIdx.x; c < pp.ncells; c += THREADS) {
        int lvl, cc, r;
        if (c < pp.n0) { lvl = 0; cc = c;          r = pp.res0; }
        else           { lvl = 1; cc = c - pp.n0;  r = pp.res1; }
        const unsigned cz  = (unsigned)(cc % r);
        const unsigned tmp = (unsigned)(cc / r);
        const unsigned cy  = tmp % (unsigned)r;
        const unsigned cx  = tmp / (unsigned)r;
        const unsigned h = (cx ^ (cy * 2654435761u) ^ (cz * 805459861u)) & HASH_MASK;
        s_tab[c] = __ldcg(tb + ((size_t)lvl << 19) + h);
    }
    __syncthreads();

    // ---- Main loop: warp handles 4 points; thread owns (point sub, levels 2p,2p+1).
    const int t     = threadIdx.x;
    const int lane  = t & 31;
    const int lpair = lane & 7;
    const int sub   = lane >> 3;
    const int gw    = blockIdx.x * (THREADS >> 5) + (t >> 5);   // global warp id
    const int gstep = CTAS * (THREADS >> 5);

    const float r0f = pp.rm1[0];
    const float r1f = pp.rm1[1];

    for (int grp = gw; grp < NGROUPS; grp += gstep) {
        const size_t pbase = (size_t)grp * 4;

        // Cooperative point load: 12 lanes fetch the warp's 48B (1 wavefront),
        // coords distributed by shuffle (replaces 3 broadcast LDGs, ~6 wf).
        float v = 0.0f;
        if (lane < 12) v = __ldcs(pts + pbase * 3 + lane);
        const float x = __shfl_sync(0xffffffffu, v, sub * 3 + 0);
        const float y = __shfl_sync(0xffffffffu, v, sub * 3 + 1);
        const float z = __shfl_sync(0xffffffffu, v, sub * 3 + 2);

        // normalize [-1,1] -> [0,1], clamp (matches jnp.clip((p+1)*0.5, 0, 1))
        const float fx = fminf(fmaxf((x + 1.0f) * 0.5f, 0.0f), 1.0f);
        const float fy = fminf(fmaxf((y + 1.0f) * 0.5f, 0.0f), 1.0f);
        const float fz = fminf(fmaxf((z + 1.0f) * 0.5f, 0.0f), 1.0f);

        float2 f0, f1;
        if (lpair == 0) {
            // levels 0,1: dense smem lookup (no hash needed)
            const int r0 = pp.res0, r1 = pp.res1;
            const int i0 = ((int)(fx * r0f) * r0 + (int)(fy * r0f)) * r0 + (int)(fz * r0f);
            const int i1 = ((int)(fx * r1f) * r1 + (int)(fy * r1f)) * r1 + (int)(fz * r1f);
            f0 = s_tab[i0];
            f1 = s_tab[pp.n0 + i1];
        } else {
            const int l0 = lpair * 2;
            const int l1 = l0 + 1;
            const float ra = pp.rm1[l0];
            const unsigned h0 = (((unsigned)(fx * ra))
                              ^  ((unsigned)(fy * ra) * 2654435761u)
                              ^  ((unsigned)(fz * ra) * 805459861u)) & HASH_MASK;
            const float rb = pp.rm1[l1];
            const unsigned h1 = (((unsigned)(fx * rb))
                              ^  ((unsigned)(fy * rb) * 2654435761u)
                              ^  ((unsigned)(fz * rb) * 805459861u)) & HASH_MASK;
            if (lpair < 3) {   // levels 2..5: small footprint, keep L1
                f0 = __ldg (tb + ((size_t)l0 << 19) + h0);
                f1 = __ldg (tb + ((size_t)l1 << 19) + h1);
            } else {           // levels 6..15: bypass L1
                f0 = __ldcg(tb + ((size_t)l0 << 19) + h0);
                f1 = __ldcg(tb + ((size_t)l1 << 19) + h1);
            }
        }

        // warp writes 512B contiguous (4 points x 128B rows), streaming.
        const float4 w = make_float4(f0.x, f0.y, f1.x, f1.y);
        __stcs(reinterpret_cast<float4*>(out) + pbase * 8 + (size_t)sub * 8 + lpair, w);
    }
}

extern "C" void kernel_launch(void* const* d_in, const int* in_sizes, int n_in,
                              void* d_out, int out_size)
{
    (void)in_sizes; (void)n_in; (void)out_size;

    // numpy-identical resolution computation (double precision, same op order)
    Params pp;
    int res[NUM_LEVELS];
    const double l128 = log(128.0);
    for (int i = 0; i < NUM_LEVELS; ++i) {
        res[i] = (int)floor(16.0 * exp(((double)i * l128) / 15.0));
        pp.rm1[i] = (float)(res[i] - 1);
    }
    pp.res0   = res[0];
    pp.res1   = res[1];
    pp.n0     = res[0] * res[0] * res[0];
    pp.ncells = pp.n0 + res[1] * res[1] * res[1];

    const size_t smem_bytes = (size_t)pp.ncells * sizeof(float2);
    cudaFuncSetAttribute(hashenc_kernel,
                         cudaFuncAttributeMaxDynamicSharedMemorySize,
                         (int)smem_bytes);

    const float* pts    = (const float*)d_in[0];
    const float* tables = (const float*)d_in[1];
    float*       out    = (float*)d_out;

    hashenc_kernel<<<CTAS, THREADS, smem_bytes>>>(pts, tables, out, pp);
}

// round 8
// speedup vs baseline: 1.1454x; 1.1454x over previous
#include <cuda_runtime.h>
#include <math.h>

#define N_POINTS   4194304
#define NUM_LEVELS 16
#define HASH_MASK  ((1u << 19) - 1u)
#define THREADS    1024
#define CTAS       148
#define NGROUPS    (N_POINTS / 4)     // groups of 4 points
#define NPAIRS     (NGROUPS / 2)      // warp processes 2 groups (8 points) per iter

struct Params {
    float rm1[NUM_LEVELS];
    int   res0, res1, n0, ncells;     // dense-cache dims for levels 0,1
};

extern __shared__ float2 s_tab[];     // [res0^3 + res1^3] dense level-0/1 cache

__device__ __forceinline__ unsigned hash3(float fx, float fy, float fz, float rm1) {
    return (((unsigned)(fx * rm1))
         ^  ((unsigned)(fy * rm1) * 2654435761u)
         ^  ((unsigned)(fz * rm1) * 805459861u)) & HASH_MASK;
}

__global__ __launch_bounds__(THREADS, 1)
void hashenc_kernel(const float*  __restrict__ pts,
                    const float*  __restrict__ tables,
                    float*        __restrict__ out,
                    Params pp)
{
    const float2* tb = reinterpret_cast<const float2*>(tables);

    // ---- Build dense smem cache for levels 0,1 (once per persistent CTA).
    for (int c = threadIdx.x; c < pp.ncells; c += THREADS) {
        int lvl, cc, r;
        if (c < pp.n0) { lvl = 0; cc = c;         r = pp.res0; }
        else           { lvl = 1; cc = c - pp.n0; r = pp.res1; }
        const unsigned cz  = (unsigned)(cc % r);
        const unsigned tmp = (unsigned)(cc / r);
        const unsigned cy  = tmp % (unsigned)r;
        const unsigned cx  = tmp / (unsigned)r;
        const unsigned h = (cx ^ (cy * 2654435761u) ^ (cz * 805459861u)) & HASH_MASK;
        s_tab[c] = __ldcg(tb + ((size_t)lvl << 19) + h);
    }
    __syncthreads();

    const int t     = threadIdx.x;
    const int lane  = t & 31;
    const int lpair = lane & 7;                  // level pair 0..7
    const int sub   = lane >> 3;                 // point-within-group 0..3
    const int gw    = blockIdx.x * (THREADS >> 5) + (t >> 5);
    const int gstep = CTAS * (THREADS >> 5);

    const float r0f = pp.rm1[0], r1f = pp.rm1[1];
    const int   r0  = pp.res0,   r1  = pp.res1;
    const int   l0  = lpair * 2, l1 = l0 + 1;
    const float ra  = pp.rm1[l0], rb = pp.rm1[l1];

    for (int gp = gw; gp < NPAIRS; gp += gstep) {
        const size_t pbase = (size_t)gp * 8;

        // Broadcast point loads for both sub-groups (R6-proven: ~1 wf each).
        const size_t pA = pbase + sub, pB = pbase + 4 + sub;
        const float xA = __ldcs(pts + 3 * pA + 0);
        const float yA = __ldcs(pts + 3 * pA + 1);
        const float zA = __ldcs(pts + 3 * pA + 2);
        const float xB = __ldcs(pts + 3 * pB + 0);
        const float yB = __ldcs(pts + 3 * pB + 1);
        const float zB = __ldcs(pts + 3 * pB + 2);

        const float fxA = fminf(fmaxf((xA + 1.0f) * 0.5f, 0.0f), 1.0f);
        const float fyA = fminf(fmaxf((yA + 1.0f) * 0.5f, 0.0f), 1.0f);
        const float fzA = fminf(fmaxf((zA + 1.0f) * 0.5f, 0.0f), 1.0f);
        const float fxB = fminf(fmaxf((xB + 1.0f) * 0.5f, 0.0f), 1.0f);
        const float fyB = fminf(fmaxf((yB + 1.0f) * 0.5f, 0.0f), 1.0f);
        const float fzB = fminf(fmaxf((zB + 1.0f) * 0.5f, 0.0f), 1.0f);

        float2 f0A, f1A, f0B, f1B;
        if (lpair == 0) {
            // levels 0,1 from dense smem (no hash, no LDG)
            const int i0A = ((int)(fxA*r0f) * r0 + (int)(fyA*r0f)) * r0 + (int)(fzA*r0f);
            const int i1A = ((int)(fxA*r1f) * r1 + (int)(fyA*r1f)) * r1 + (int)(fzA*r1f);
            const int i0B = ((int)(fxB*r0f) * r0 + (int)(fyB*r0f)) * r0 + (int)(fzB*r0f);
            const int i1B = ((int)(fxB*r1f) * r1 + (int)(fyB*r1f)) * r1 + (int)(fzB*r1f);
            f0A = s_tab[i0A];  f1A = s_tab[pp.n0 + i1A];
            f0B = s_tab[i0B];  f1B = s_tab[pp.n0 + i1B];
        } else {
            const unsigned h0A = hash3(fxA, fyA, fzA, ra);
            const unsigned h1A = hash3(fxA, fyA, fzA, rb);
            const unsigned h0B = hash3(fxB, fyB, fzB, ra);
            const unsigned h1B = hash3(fxB, fyB, fzB, rb);
            const float2* q0A = tb + ((size_t)l0 << 19) + h0A;
            const float2* q1A = tb + ((size_t)l1 << 19) + h1A;
            const float2* q0B = tb + ((size_t)l0 << 19) + h0B;
            const float2* q1B = tb + ((size_t)l1 << 19) + h1B;
            if (lpair < 3) {               // levels 2..5: small, keep L1
                f0A = __ldg(q0A);  f1A = __ldg(q1A);
                f0B = __ldg(q0B);  f1B = __ldg(q1B);
            } else {                       // levels 6..15: bypass L1
                f0A = __ldcg(q0A); f1A = __ldcg(q1A);
                f0B = __ldcg(q0B); f1B = __ldcg(q1B);
            }
        }

        // two coalesced 512B warp stores, streaming
        float4* ob = reinterpret_cast<float4*>(out);
        __stcs(ob + pA * 8 + lpair, make_float4(f0A.x, f0A.y, f1A.x, f1A.y));
        __stcs(ob + pB * 8 + lpair, make_float4(f0B.x, f0B.y, f1B.x, f1B.y));
    }
}

extern "C" void kernel_launch(void* const* d_in, const int* in_sizes, int n_in,
                              void* d_out, int out_size)
{
    (void)in_sizes; (void)n_in; (void)out_size;

    // numpy-identical resolution computation (double precision, same op order)
    Params pp;
    int res[NUM_LEVELS];
    const double l128 = log(128.0);
    for (int i = 0; i < NUM_LEVELS; ++i) {
        res[i] = (int)floor(16.0 * exp(((double)i * l128) / 15.0));
        pp.rm1[i] = (float)(res[i] - 1);
    }
    pp.res0   = res[0];
    pp.res1   = res[1];
    pp.n0     = res[0] * res[0] * res[0];
    pp.ncells = pp.n0 + res[1] * res[1] * res[1];

    const size_t smem_bytes = (size_t)pp.ncells * sizeof(float2);
    cudaFuncSetAttribute(hashenc_kernel,
                         cudaFuncAttributeMaxDynamicSharedMemorySize,
                         (int)smem_bytes);

    const float* pts    = (const float*)d_in[0];
    const float* tables = (const float*)d_in[1];
    float*       out    = (float*)d_out;

    hashenc_kernel<<<CTAS, THREADS, smem_bytes>>>(pts, tables, out, pp);
}